// round 5
// baseline (speedup 1.0000x reference)
#include <cuda_runtime.h>
#include <cuda_bf16.h>
#include <stdint.h>

// ============================================================================
// LocalGNNBranch: 3-layer GraphSAGE, N=100k, E=1.6M, D=64, B=64. All fp32.
//  - CSR: hist -> single-pass decoupled-lookback scan -> fill(+stateclr)
//  - 3x fused k_layer: CSR gather-mean into smem z-tile, then FFMA2 GEMM
//    + bias + L2norm + ReLU (R2-proven inner loop). No g_mean round-trip.
//  - sum-pool readout.
// 7 launches total; k_layer sits at capture index 3 for ncu.
// ============================================================================

#define MAXN 100000
#define MAXE 1600000
#define DF   64
#define KK   128         // GEMM K = 2*DF (mean || x)
#define NT   128         // nodes per block
#define WS   66          // w_s row stride
#define ZS   130         // z_s row stride
#define SCAN_CHUNK 1024
#define MAXBLK 128

typedef unsigned long long ull;

// ---- static device scratch ----
__device__ float g_h1[(size_t)MAXN * DF];
__device__ float g_h2[(size_t)MAXN * DF];
__device__ int   g_deg[MAXN];
__device__ int   g_rowstart[MAXN + 1];
__device__ int   g_cursor[MAXN];
__device__ int   g_csr[MAXE];
__device__ ull   g_scanstate[MAXBLK];   // (sum<<2)|flag ; 0=inv,1=partial,2=incl

// ---- helpers ----
__device__ __forceinline__ ull pk2(float lo, float hi) {
    ull r; asm("mov.b64 %0, {%1, %2};" : "=l"(r) : "f"(lo), "f"(hi)); return r;
}
__device__ __forceinline__ void fma2(ull& d, ull a, ull b) {
    asm("fma.rn.f32x2 %0, %1, %2, %0;" : "+l"(d) : "l"(a), "l"(b));
}
__device__ __forceinline__ float2 up2(ull v) {
    float2 f; asm("mov.b64 {%0, %1}, %2;" : "=f"(f.x), "=f"(f.y) : "l"(v)); return f;
}
__device__ __forceinline__ void st_rel(ull* p, ull v) {
    asm volatile("st.global.release.gpu.u64 [%0], %1;" :: "l"(p), "l"(v) : "memory");
}
__device__ __forceinline__ ull ld_acq(const ull* p) {
    ull v; asm volatile("ld.global.acquire.gpu.u64 %0, [%1];" : "=l"(v) : "l"(p) : "memory");
    return v;
}

// ---------------------------------------------------------------------------
__global__ void k_hist(const int* __restrict__ dst, int e) {
    int i = blockIdx.x * blockDim.x + threadIdx.x;
    if (i < e) atomicAdd(&g_deg[dst[i]], 1);
}

// Single-pass scan, decoupled lookback. Writes rowstart + sentinel, cursor=rowstart,
// resets deg=0 for the next replay. scanstate zeroed by k_fill each replay.
__global__ __launch_bounds__(256) void k_scan(int n, int nblk) {
    __shared__ int s[256];
    __shared__ int s_prefix;
    int b = blockIdx.x, tid = threadIdx.x;
    int base = b * SCAN_CHUNK + tid * 4;
    int v[4];
    int tsum = 0;
#pragma unroll
    for (int i = 0; i < 4; i++) {
        int gi = base + i;
        v[i] = (gi < n) ? g_deg[gi] : 0;
        tsum += v[i];
    }
    s[tid] = tsum;
    __syncthreads();
    for (int d = 1; d < 256; d <<= 1) {
        int t = (tid >= d) ? s[tid - d] : 0;
        __syncthreads();
        s[tid] += t;
        __syncthreads();
    }
    int total = s[255];
    if (tid == 0) {
        st_rel(&g_scanstate[b], ((ull)total << 2) | 1ull);
        ull prefix = 0;
        int j = b - 1;
        while (j >= 0) {
            ull st = ld_acq(&g_scanstate[j]);
            ull f = st & 3ull;
            if (f == 0) continue;
            prefix += st >> 2;
            if (f == 2) break;
            j--;
        }
        st_rel(&g_scanstate[b], ((prefix + (ull)total) << 2) | 2ull);
        s_prefix = (int)prefix;
    }
    __syncthreads();
    int run = s_prefix + s[tid] - tsum;
#pragma unroll
    for (int i = 0; i < 4; i++) {
        int gi = base + i;
        if (gi < n) {
            g_rowstart[gi] = run;
            g_cursor[gi] = run;
            g_deg[gi] = 0;
            run += v[i];
        }
    }
    if (b == nblk - 1 && tid == 255) g_rowstart[n] = s_prefix + total;
}

// fill CSR; also reset scanstate for the next replay (scan already consumed it).
__global__ void k_fill(const int* __restrict__ src, const int* __restrict__ dst, int e) {
    if (blockIdx.x == 0 && threadIdx.x < MAXBLK) g_scanstate[threadIdx.x] = 0;
    int i = blockIdx.x * blockDim.x + threadIdx.x;
    if (i < e) {
        int d = dst[i];
        int p = atomicAdd(&g_cursor[d], 1);
        g_csr[p] = src[i];
    }
}

// ---------------------------------------------------------------------------
// Fused layer: z = [mean(neigh(x)) || x] built in smem, then
// out = relu(l2norm(z @ [Wl;Wr]^T + bl)).
// 256 threads, 128 nodes/block; agg: 16 thr/node (8 passes); gemm: 4 nodes x
// 8 outs per thread via FFMA2.
__global__ __launch_bounds__(256, 2) void k_layer(const float* __restrict__ xin,
                                                  const float* __restrict__ Wl,
                                                  const float* __restrict__ bl,
                                                  const float* __restrict__ Wr,
                                                  float* __restrict__ out, int n) {
    extern __shared__ float smem[];
    float* w_s = smem;              // [KK][WS]
    float* z_s = smem + KK * WS;    // [NT][ZS]: [0..63]=mean, [64..127]=x
    int tid = threadIdx.x;

    // ---- weights, transposed ----
    for (int i = tid; i < DF * DF; i += 256) {
        int o = i >> 6, k = i & 63;
        w_s[k * WS + o]        = Wl[i];
        w_s[(k + DF) * WS + o] = Wr[i];
    }

    int nodeBase = blockIdx.x * NT;
    const float4* xv = (const float4*)xin;

    // ---- aggregation phase: 16 threads/node, float4 each, MLP=4 ----
    int c = tid & 15;
    int nloc = tid >> 4;    // 0..15
#pragma unroll 1
    for (int p = 0; p < 8; p++) {
        int nl = p * 16 + nloc;
        int gn = nodeBase + nl;
        float4 acc = make_float4(0.f, 0.f, 0.f, 0.f);
        float4 root = acc;
        if (gn < n) {
            int base = g_rowstart[gn];
            int dg = g_rowstart[gn + 1] - base;
            const int* cp = g_csr + base;
            float4 a0 = acc, a1 = acc, a2 = acc, a3 = acc;
            int k = 0;
            for (; k + 4 <= dg; k += 4) {
                int s0 = __ldg(cp + k + 0) * 16 + c;
                int s1 = __ldg(cp + k + 1) * 16 + c;
                int s2 = __ldg(cp + k + 2) * 16 + c;
                int s3 = __ldg(cp + k + 3) * 16 + c;
                float4 v0 = __ldg(xv + s0);
                float4 v1 = __ldg(xv + s1);
                float4 v2 = __ldg(xv + s2);
                float4 v3 = __ldg(xv + s3);
                a0.x += v0.x; a0.y += v0.y; a0.z += v0.z; a0.w += v0.w;
                a1.x += v1.x; a1.y += v1.y; a1.z += v1.z; a1.w += v1.w;
                a2.x += v2.x; a2.y += v2.y; a2.z += v2.z; a2.w += v2.w;
                a3.x += v3.x; a3.y += v3.y; a3.z += v3.z; a3.w += v3.w;
            }
            for (; k < dg; k++) {
                int s = __ldg(cp + k) * 16 + c;
                float4 v = __ldg(xv + s);
                a0.x += v.x; a0.y += v.y; a0.z += v.z; a0.w += v.w;
            }
            acc.x = (a0.x + a1.x) + (a2.x + a3.x);
            acc.y = (a0.y + a1.y) + (a2.y + a3.y);
            acc.z = (a0.z + a1.z) + (a2.z + a3.z);
            acc.w = (a0.w + a1.w) + (a2.w + a3.w);
            float invd = 1.0f / (float)max(dg, 1);
            acc.x *= invd; acc.y *= invd; acc.z *= invd; acc.w *= invd;
            root = __ldg(xv + gn * 16 + c);
        }
        float* zp = z_s + nl * ZS + c * 4;
        zp[0] = acc.x; zp[1] = acc.y; zp[2] = acc.z; zp[3] = acc.w;
        float* rp = zp + DF;
        rp[0] = root.x; rp[1] = root.y; rp[2] = root.z; rp[3] = root.w;
    }
    __syncthreads();

    // ---- GEMM phase (R2-proven) ----
    int og = tid & 7;
    int ng = tid >> 3;
    int nrow = ng * 4;

    const float* bp = bl + og * 8;
    ull acc[4][4];
    {
        ull b0 = pk2(bp[0], bp[1]), b1 = pk2(bp[2], bp[3]);
        ull b2 = pk2(bp[4], bp[5]), b3 = pk2(bp[6], bp[7]);
#pragma unroll
        for (int nn = 0; nn < 4; nn++) {
            acc[nn][0] = b0; acc[nn][1] = b1; acc[nn][2] = b2; acc[nn][3] = b3;
        }
    }

    const float* zb = z_s + nrow * ZS;
    const float* wb = w_s + og * 8;
#pragma unroll 4
    for (int k = 0; k < KK; k++) {
        ull zz0 = pk2(zb[0 * ZS + k], zb[0 * ZS + k]);
        ull zz1 = pk2(zb[1 * ZS + k], zb[1 * ZS + k]);
        ull zz2 = pk2(zb[2 * ZS + k], zb[2 * ZS + k]);
        ull zz3 = pk2(zb[3 * ZS + k], zb[3 * ZS + k]);
        const float* wr_ = wb + k * WS;
        ull w0 = *(const ull*)(wr_ + 0);
        ull w1 = *(const ull*)(wr_ + 2);
        ull w2 = *(const ull*)(wr_ + 4);
        ull w3 = *(const ull*)(wr_ + 6);
        fma2(acc[0][0], zz0, w0); fma2(acc[0][1], zz0, w1);
        fma2(acc[0][2], zz0, w2); fma2(acc[0][3], zz0, w3);
        fma2(acc[1][0], zz1, w0); fma2(acc[1][1], zz1, w1);
        fma2(acc[1][2], zz1, w2); fma2(acc[1][3], zz1, w3);
        fma2(acc[2][0], zz2, w0); fma2(acc[2][1], zz2, w1);
        fma2(acc[2][2], zz2, w2); fma2(acc[2][3], zz2, w3);
        fma2(acc[3][0], zz3, w0); fma2(acc[3][1], zz3, w1);
        fma2(acc[3][2], zz3, w2); fma2(acc[3][3], zz3, w3);
    }

#pragma unroll
    for (int nn = 0; nn < 4; nn++) {
        float2 f0 = up2(acc[nn][0]), f1 = up2(acc[nn][1]);
        float2 f2 = up2(acc[nn][2]), f3 = up2(acc[nn][3]);
        float sq = f0.x * f0.x + f0.y * f0.y + f1.x * f1.x + f1.y * f1.y
                 + f2.x * f2.x + f2.y * f2.y + f3.x * f3.x + f3.y * f3.y;
        sq += __shfl_xor_sync(0xffffffffu, sq, 1);
        sq += __shfl_xor_sync(0xffffffffu, sq, 2);
        sq += __shfl_xor_sync(0xffffffffu, sq, 4);
        float scale = 1.0f / fmaxf(sqrtf(sq), 1e-12f);
        int node = nodeBase + nrow + nn;
        if (node < n) {
            float4 o0 = make_float4(fmaxf(f0.x * scale, 0.f), fmaxf(f0.y * scale, 0.f),
                                    fmaxf(f1.x * scale, 0.f), fmaxf(f1.y * scale, 0.f));
            float4 o1 = make_float4(fmaxf(f2.x * scale, 0.f), fmaxf(f2.y * scale, 0.f),
                                    fmaxf(f3.x * scale, 0.f), fmaxf(f3.y * scale, 0.f));
            float4* op = (float4*)(out + (size_t)node * DF + og * 8);
            op[0] = o0; op[1] = o1;
        }
    }
}

// ---------------------------------------------------------------------------
__device__ __forceinline__ int lower_bound_i(const int* __restrict__ a, int n, int v) {
    int lo = 0, hi = n;
    while (lo < hi) {
        int m = (lo + hi) >> 1;
        if (a[m] < v) lo = m + 1; else hi = m;
    }
    return lo;
}

__global__ __launch_bounds__(256) void k_pool(const float* __restrict__ h,
                                              const int* __restrict__ batch,
                                              float* __restrict__ out, int n) {
    __shared__ int s_lo, s_hi;
    __shared__ float red[4][DF];
    int b = blockIdx.x;
    if (threadIdx.x == 0) {
        s_lo = lower_bound_i(batch, n, b);
        s_hi = lower_bound_i(batch, n, b + 1);
    }
    __syncthreads();
    int lo = s_lo, hi = s_hi;
    int f = threadIdx.x & 63;
    int lane = threadIdx.x >> 6;
    float acc = 0.f;
    for (int nd = lo + lane; nd < hi; nd += 4)
        acc += h[(size_t)nd * DF + f];
    red[lane][f] = acc;
    __syncthreads();
    if (lane == 0)
        out[b * DF + f] = red[0][f] + red[1][f] + red[2][f] + red[3][f];
}

// ---------------------------------------------------------------------------
extern "C" void kernel_launch(void* const* d_in, const int* in_sizes, int n_in,
                              void* d_out, int out_size) {
    const float* x_raw = (const float*)d_in[0];
    const int*   ei    = (const int*)d_in[1];
    const int*   batch = (const int*)d_in[2];
    const float* W[9];
    for (int i = 0; i < 9; i++) W[i] = (const float*)d_in[3 + i];

    int n = in_sizes[0] / DF;
    int e = in_sizes[1] / 2;
    int b = out_size / DF;
    const int* src = ei;
    const int* dst = ei + e;
    float* out = (float*)d_out;

    int nblk = (n + SCAN_CHUNK - 1) / SCAN_CHUNK;   // 98

    static int smem_set = 0;
    const int LAYER_SMEM = (KK * WS + NT * ZS) * 4;   // 100,352 bytes
    if (!smem_set) {
        cudaFuncSetAttribute(k_layer, cudaFuncAttributeMaxDynamicSharedMemorySize,
                             LAYER_SMEM);
        smem_set = 1;
    }

    // ---- CSR build: 3 launches ----
    k_hist<<<(e + 255) / 256, 256>>>(dst, e);          // 0
    k_scan<<<nblk, 256>>>(n, nblk);                    // 1
    k_fill<<<(e + 255) / 256, 256>>>(src, dst, e);     // 2

    float* h1; cudaGetSymbolAddress((void**)&h1, g_h1);
    float* h2; cudaGetSymbolAddress((void**)&h2, g_h2);

    int grid = (n + NT - 1) / NT;

    k_layer<<<grid, 256, LAYER_SMEM>>>(x_raw, W[0], W[1], W[2], h1, n);  // 3 <- ncu
    k_layer<<<grid, 256, LAYER_SMEM>>>(h1,    W[3], W[4], W[5], h2, n);  // 4
    k_layer<<<grid, 256, LAYER_SMEM>>>(h2,    W[6], W[7], W[8], h1, n);  // 5

    k_pool<<<b, 256>>>(h1, batch, out, n);                               // 6
}

// round 8
// speedup vs baseline: 1.1855x; 1.1855x over previous
#include <cuda_runtime.h>
#include <cuda_bf16.h>
#include <stdint.h>

// ============================================================================
// LocalGNNBranch: 3-layer GraphSAGE, N=100k, E=1.6M, D=64, B=64. All fp32.
//  - CSR: hist -> decoupled-lookback scan -> fill(+stateclr)
//  - 3x [gather-mean agg (MLP=8) -> FFMA2 GEMM v3 (all-conflict-free LDS/STS)]
//  - sum-pool readout
// GEMM v3: 128 nodes x 64 outs/block, thread = 4 nodes x 8 outs.
//   acc packed as OUTPUT pairs: acc[nn][p] = (out og*8+2p, og*8+2p+1).
//   z: scalar LDS (conflict-free) + mov dup; w: LDS.64 interleaved conflict-free.
//   Transpose prologue: STS banks = 8*cq + node + 2*i2 -> 32 distinct, no conflicts.
// ============================================================================

#define MAXN 100000
#define MAXE 1600000
#define DF   64
#define KK   128         // GEMM K = 2*DF (mean || x)
#define NT   128         // nodes per GEMM block
#define WS   66          // w_s k-row stride (floats), even for 8B-aligned LDS.64
#define ZS2  130         // z_s k-row stride (floats)
#define SCAN_CHUNK 1024
#define MAXBLK 128

typedef unsigned long long ull;

// ---- static device scratch ----
__device__ float g_mean[(size_t)MAXN * DF];
__device__ float g_h1[(size_t)MAXN * DF];
__device__ float g_h2[(size_t)MAXN * DF];
__device__ int   g_deg[MAXN];
__device__ int   g_rowstart[MAXN + 1];
__device__ int   g_cursor[MAXN];
__device__ int   g_csr[MAXE];
__device__ ull   g_scanstate[MAXBLK];

// ---- helpers ----
__device__ __forceinline__ ull pk2(float lo, float hi) {
    ull r; asm("mov.b64 %0, {%1, %2};" : "=l"(r) : "f"(lo), "f"(hi)); return r;
}
__device__ __forceinline__ void fma2(ull& d, ull a, ull b) {
    asm("fma.rn.f32x2 %0, %1, %2, %0;" : "+l"(d) : "l"(a), "l"(b));
}
__device__ __forceinline__ float2 up2(ull v) {
    float2 f; asm("mov.b64 {%0, %1}, %2;" : "=f"(f.x), "=f"(f.y) : "l"(v)); return f;
}
__device__ __forceinline__ void st_rel(ull* p, ull v) {
    asm volatile("st.global.release.gpu.u64 [%0], %1;" :: "l"(p), "l"(v) : "memory");
}
__device__ __forceinline__ ull ld_acq(const ull* p) {
    ull v; asm volatile("ld.global.acquire.gpu.u64 %0, [%1];" : "=l"(v) : "l"(p) : "memory");
    return v;
}

// ---------------------------------------------------------------------------
__global__ void k_hist(const int* __restrict__ dst, int e) {
    int i = blockIdx.x * blockDim.x + threadIdx.x;
    if (i < e) atomicAdd(&g_deg[dst[i]], 1);
}

__global__ __launch_bounds__(256) void k_scan(int n, int nblk) {
    __shared__ int s[256];
    __shared__ int s_prefix;
    int b = blockIdx.x, tid = threadIdx.x;
    int base = b * SCAN_CHUNK + tid * 4;
    int v[4];
    int tsum = 0;
#pragma unroll
    for (int i = 0; i < 4; i++) {
        int gi = base + i;
        v[i] = (gi < n) ? g_deg[gi] : 0;
        tsum += v[i];
    }
    s[tid] = tsum;
    __syncthreads();
    for (int d = 1; d < 256; d <<= 1) {
        int t = (tid >= d) ? s[tid - d] : 0;
        __syncthreads();
        s[tid] += t;
        __syncthreads();
    }
    int total = s[255];
    if (tid == 0) {
        st_rel(&g_scanstate[b], ((ull)total << 2) | 1ull);
        ull prefix = 0;
        int j = b - 1;
        while (j >= 0) {
            ull st = ld_acq(&g_scanstate[j]);
            ull f = st & 3ull;
            if (f == 0) continue;
            prefix += st >> 2;
            if (f == 2) break;
            j--;
        }
        st_rel(&g_scanstate[b], ((prefix + (ull)total) << 2) | 2ull);
        s_prefix = (int)prefix;
    }
    __syncthreads();
    int run = s_prefix + s[tid] - tsum;
#pragma unroll
    for (int i = 0; i < 4; i++) {
        int gi = base + i;
        if (gi < n) {
            g_rowstart[gi] = run;
            g_cursor[gi] = run;
            g_deg[gi] = 0;
            run += v[i];
        }
    }
    if (b == nblk - 1 && tid == 255) g_rowstart[n] = s_prefix + total;
}

// fill CSR; block 0 also resets scanstate for the next replay.
__global__ void k_fill(const int* __restrict__ src, const int* __restrict__ dst, int e) {
    if (blockIdx.x == 0 && threadIdx.x < MAXBLK) g_scanstate[threadIdx.x] = 0;
    int i = blockIdx.x * blockDim.x + threadIdx.x;
    if (i < e) {
        int d = dst[i];
        int p = atomicAdd(&g_cursor[d], 1);
        g_csr[p] = src[i];
    }
}

// ---------------------------------------------------------------------------
// Aggregation: mean of neighbors. 16 threads/node, float4 each, MLP=8, int32 math.
__global__ __launch_bounds__(256) void k_agg(const float* __restrict__ x,
                                             float* __restrict__ meanout, int n) {
    int t = blockIdx.x * blockDim.x + threadIdx.x;
    int node = t >> 4;
    int c = t & 15;
    if (node >= n) return;
    int base = g_rowstart[node];
    int dg = g_rowstart[node + 1] - base;
    const float4* xv = (const float4*)x;
    const int* cp = g_csr + base;
    float4 a0 = make_float4(0.f, 0.f, 0.f, 0.f);
    float4 a1 = a0, a2 = a0, a3 = a0;
    int k = 0;
    for (; k + 8 <= dg; k += 8) {
        int s0 = __ldg(cp + k + 0) * 16 + c;
        int s1 = __ldg(cp + k + 1) * 16 + c;
        int s2 = __ldg(cp + k + 2) * 16 + c;
        int s3 = __ldg(cp + k + 3) * 16 + c;
        int s4 = __ldg(cp + k + 4) * 16 + c;
        int s5 = __ldg(cp + k + 5) * 16 + c;
        int s6 = __ldg(cp + k + 6) * 16 + c;
        int s7 = __ldg(cp + k + 7) * 16 + c;
        float4 v0 = __ldg(xv + s0);
        float4 v1 = __ldg(xv + s1);
        float4 v2 = __ldg(xv + s2);
        float4 v3 = __ldg(xv + s3);
        float4 v4 = __ldg(xv + s4);
        float4 v5 = __ldg(xv + s5);
        float4 v6 = __ldg(xv + s6);
        float4 v7 = __ldg(xv + s7);
        a0.x += v0.x; a0.y += v0.y; a0.z += v0.z; a0.w += v0.w;
        a1.x += v1.x; a1.y += v1.y; a1.z += v1.z; a1.w += v1.w;
        a2.x += v2.x; a2.y += v2.y; a2.z += v2.z; a2.w += v2.w;
        a3.x += v3.x; a3.y += v3.y; a3.z += v3.z; a3.w += v3.w;
        a0.x += v4.x; a0.y += v4.y; a0.z += v4.z; a0.w += v4.w;
        a1.x += v5.x; a1.y += v5.y; a1.z += v5.z; a1.w += v5.w;
        a2.x += v6.x; a2.y += v6.y; a2.z += v6.z; a2.w += v6.w;
        a3.x += v7.x; a3.y += v7.y; a3.z += v7.z; a3.w += v7.w;
    }
    for (; k + 4 <= dg; k += 4) {
        int s0 = __ldg(cp + k + 0) * 16 + c;
        int s1 = __ldg(cp + k + 1) * 16 + c;
        int s2 = __ldg(cp + k + 2) * 16 + c;
        int s3 = __ldg(cp + k + 3) * 16 + c;
        float4 v0 = __ldg(xv + s0);
        float4 v1 = __ldg(xv + s1);
        float4 v2 = __ldg(xv + s2);
        float4 v3 = __ldg(xv + s3);
        a0.x += v0.x; a0.y += v0.y; a0.z += v0.z; a0.w += v0.w;
        a1.x += v1.x; a1.y += v1.y; a1.z += v1.z; a1.w += v1.w;
        a2.x += v2.x; a2.y += v2.y; a2.z += v2.z; a2.w += v2.w;
        a3.x += v3.x; a3.y += v3.y; a3.z += v3.z; a3.w += v3.w;
    }
    for (; k < dg; k++) {
        int s = __ldg(cp + k) * 16 + c;
        float4 v = __ldg(xv + s);
        a0.x += v.x; a0.y += v.y; a0.z += v.z; a0.w += v.w;
    }
    float4 acc;
    acc.x = (a0.x + a1.x) + (a2.x + a3.x);
    acc.y = (a0.y + a1.y) + (a2.y + a3.y);
    acc.z = (a0.z + a1.z) + (a2.z + a3.z);
    acc.w = (a0.w + a1.w) + (a2.w + a3.w);
    float invd = 1.0f / (float)max(dg, 1);
    acc.x *= invd; acc.y *= invd; acc.z *= invd; acc.w *= invd;
    ((float4*)meanout)[node * 16 + c] = acc;
}

// ---------------------------------------------------------------------------
// GEMM v3: out = relu(l2norm([mean||x] @ [Wl;Wr]^T + bl))
// 256 threads, 128 nodes x 64 outs/block; thread = 4 nodes x 8 outs.
// w_s[k][pos], pos(o) = ((o&7)>>1)*16 + (o>>3)*2 + (o&1)  (conflict-free LDS.64)
// z_s[k][node] transpose, conflict-free STS (banks 8*cq+node+2*i2) and LDS.
__global__ __launch_bounds__(256, 2) void k_gemm(const float* __restrict__ mean,
                                                 const float* __restrict__ xin,
                                                 const float* __restrict__ Wl,
                                                 const float* __restrict__ bl,
                                                 const float* __restrict__ Wr,
                                                 float* __restrict__ out, int n) {
    extern __shared__ float smem[];
    float* w_s = smem;               // [KK][WS]
    float* z_s = smem + KK * WS;     // [KK][ZS2], z[k][node]
    int tid = threadIdx.x;

    // ---- weights: pos(o) = ((o&7)>>1)*16 + (o>>3)*2 + (o&1) ----
    for (int i = tid; i < DF * DF; i += 256) {
        int o = i >> 6, k = i & 63;
        int pos = (((o & 7) >> 1) << 4) + ((o >> 3) << 1) + (o & 1);
        w_s[k * WS + pos]        = Wl[i];
        w_s[(k + DF) * WS + pos] = Wr[i];
    }

    int nodeBase = blockIdx.x * NT;
    // ---- z transpose prologue: warp = 8 nodes x 4 k-quads, conflict-free STS ----
    {
        int nl_lo = tid & 7;           // node low bits
        int cq    = (tid >> 3) & 31;   // k-quad 0..31 (k = cq*4 + i2)
#pragma unroll 4
        for (int it = 0; it < 16; it++) {
            int nl = it * 8 + nl_lo;   // 0..127
            int gn = nodeBase + nl;
            float4 v = make_float4(0.f, 0.f, 0.f, 0.f);
            if (gn < n) {
                const float4* p = (cq < 16)
                    ? ((const float4*)(mean + (size_t)gn * DF) + cq)
                    : ((const float4*)(xin + (size_t)gn * DF) + (cq - 16));
                v = __ldg(p);
            }
            int k0 = cq * 4;
            z_s[(k0 + 0) * ZS2 + nl] = v.x;
            z_s[(k0 + 1) * ZS2 + nl] = v.y;
            z_s[(k0 + 2) * ZS2 + nl] = v.z;
            z_s[(k0 + 3) * ZS2 + nl] = v.w;
        }
    }
    __syncthreads();

    int og = tid & 7;        // outputs og*8 .. og*8+7
    int ng = tid >> 3;       // 0..31 -> nodes ng*4 .. ng*4+3
    int n0 = ng * 4;         // <= 124, in-bounds

    // acc[nn][p] = (out og*8+2p, og*8+2p+1) for node n0+nn; bias via LDG.64
    ull acc[4][4];
    {
        const ull* bp = (const ull*)(bl + og * 8);
        ull b0 = bp[0], b1 = bp[1], b2 = bp[2], b3 = bp[3];
#pragma unroll
        for (int nn = 0; nn < 4; nn++) {
            acc[nn][0] = b0; acc[nn][1] = b1; acc[nn][2] = b2; acc[nn][3] = b3;
        }
    }

#pragma unroll 4
    for (int k = 0; k < KK; k++) {
        const float* zr = z_s + k * ZS2 + n0;
        float za = zr[0], zb = zr[1], zc = zr[2], zd = zr[3];
        ull z0 = pk2(za, za);
        ull z1 = pk2(zb, zb);
        ull z2 = pk2(zc, zc);
        ull z3 = pk2(zd, zd);
        const float* wr_ = w_s + k * WS + og * 2;
        ull w0 = *(const ull*)(wr_ + 0);
        ull w1 = *(const ull*)(wr_ + 16);
        ull w2 = *(const ull*)(wr_ + 32);
        ull w3 = *(const ull*)(wr_ + 48);
        fma2(acc[0][0], z0, w0); fma2(acc[0][1], z0, w1);
        fma2(acc[0][2], z0, w2); fma2(acc[0][3], z0, w3);
        fma2(acc[1][0], z1, w0); fma2(acc[1][1], z1, w1);
        fma2(acc[1][2], z1, w2); fma2(acc[1][3], z1, w3);
        fma2(acc[2][0], z2, w0); fma2(acc[2][1], z2, w1);
        fma2(acc[2][2], z2, w2); fma2(acc[2][3], z2, w3);
        fma2(acc[3][0], z3, w0); fma2(acc[3][1], z3, w1);
        fma2(acc[3][2], z3, w2); fma2(acc[3][3], z3, w3);
    }

    // ---- epilogue: per-node L2 norm (acc halves are same-node outputs) ----
#pragma unroll
    for (int nn = 0; nn < 4; nn++) {
        ull sq2 = pk2(0.f, 0.f);
#pragma unroll
        for (int p = 0; p < 4; p++) fma2(sq2, acc[nn][p], acc[nn][p]);
        float2 sf = up2(sq2);
        float sq = sf.x + sf.y;
        sq += __shfl_xor_sync(0xffffffffu, sq, 1);
        sq += __shfl_xor_sync(0xffffffffu, sq, 2);
        sq += __shfl_xor_sync(0xffffffffu, sq, 4);
        float scale = 1.0f / fmaxf(sqrtf(sq), 1e-12f);
        int node = nodeBase + n0 + nn;
        if (node < n) {
            float2 f0 = up2(acc[nn][0]), f1 = up2(acc[nn][1]);
            float2 f2 = up2(acc[nn][2]), f3 = up2(acc[nn][3]);
            float4 o0 = make_float4(fmaxf(f0.x * scale, 0.f), fmaxf(f0.y * scale, 0.f),
                                    fmaxf(f1.x * scale, 0.f), fmaxf(f1.y * scale, 0.f));
            float4 o1 = make_float4(fmaxf(f2.x * scale, 0.f), fmaxf(f2.y * scale, 0.f),
                                    fmaxf(f3.x * scale, 0.f), fmaxf(f3.y * scale, 0.f));
            float4* op = (float4*)(out + (size_t)node * DF + og * 8);
            op[0] = o0; op[1] = o1;
        }
    }
}

// ---------------------------------------------------------------------------
__device__ __forceinline__ int lower_bound_i(const int* __restrict__ a, int n, int v) {
    int lo = 0, hi = n;
    while (lo < hi) {
        int m = (lo + hi) >> 1;
        if (a[m] < v) lo = m + 1; else hi = m;
    }
    return lo;
}

__global__ __launch_bounds__(256) void k_pool(const float* __restrict__ h,
                                              const int* __restrict__ batch,
                                              float* __restrict__ out, int n) {
    __shared__ int s_lo, s_hi;
    __shared__ float red[4][DF];
    int b = blockIdx.x;
    if (threadIdx.x == 0) {
        s_lo = lower_bound_i(batch, n, b);
        s_hi = lower_bound_i(batch, n, b + 1);
    }
    __syncthreads();
    int lo = s_lo, hi = s_hi;
    int f = threadIdx.x & 63;
    int lane = threadIdx.x >> 6;
    float acc = 0.f;
    for (int nd = lo + lane; nd < hi; nd += 4)
        acc += h[(size_t)nd * DF + f];
    red[lane][f] = acc;
    __syncthreads();
    if (lane == 0)
        out[b * DF + f] = red[0][f] + red[1][f] + red[2][f] + red[3][f];
}

// ---------------------------------------------------------------------------
extern "C" void kernel_launch(void* const* d_in, const int* in_sizes, int n_in,
                              void* d_out, int out_size) {
    const float* x_raw = (const float*)d_in[0];
    const int*   ei    = (const int*)d_in[1];
    const int*   batch = (const int*)d_in[2];
    const float* W[9];
    for (int i = 0; i < 9; i++) W[i] = (const float*)d_in[3 + i];

    int n = in_sizes[0] / DF;
    int e = in_sizes[1] / 2;
    int b = out_size / DF;
    const int* src = ei;
    const int* dst = ei + e;
    float* out = (float*)d_out;

    int nblk = (n + SCAN_CHUNK - 1) / SCAN_CHUNK;   // 98

    static int smem_set = 0;
    const int GEMM_SMEM = (KK * WS + KK * ZS2) * 4;   // 100,352 bytes
    if (!smem_set) {
        cudaFuncSetAttribute(k_gemm, cudaFuncAttributeMaxDynamicSharedMemorySize,
                             GEMM_SMEM);
        smem_set = 1;
    }

    // ---- CSR build ----
    k_hist<<<(e + 255) / 256, 256>>>(dst, e);          // 0
    k_scan<<<nblk, 256>>>(n, nblk);                    // 1
    k_fill<<<(e + 255) / 256, 256>>>(src, dst, e);     // 2

    float* mean; cudaGetSymbolAddress((void**)&mean, g_mean);
    float* h1;   cudaGetSymbolAddress((void**)&h1, g_h1);
    float* h2;   cudaGetSymbolAddress((void**)&h2, g_h2);

    int aggGrid  = (n * 16 + 255) / 256;
    int gemmGrid = (n + NT - 1) / NT;

    k_agg<<<aggGrid, 256>>>(x_raw, mean, n);                                     // 3
    k_gemm<<<gemmGrid, 256, GEMM_SMEM>>>(mean, x_raw, W[0], W[1], W[2], h1, n);  // 4
    k_agg<<<aggGrid, 256>>>(h1, mean, n);
    k_gemm<<<gemmGrid, 256, GEMM_SMEM>>>(mean, h1, W[3], W[4], W[5], h2, n);
    k_agg<<<aggGrid, 256>>>(h2, mean, n);
    k_gemm<<<gemmGrid, 256, GEMM_SMEM>>>(mean, h2, W[6], W[7], W[8], h1, n);

    k_pool<<<b, 256>>>(h1, batch, out, n);
}